// round 9
// baseline (speedup 1.0000x reference)
#include <cuda_runtime.h>
#include <math.h>

// Problem shape (fixed by the dataset)
#define NROWS   32768      // B*T = 4*8192
#define DDIM    1024
#define KD      6
#define NP      8
#define ROWS_PER_WARP 4
#define THREADS 256
#define WARPS_PER_BLOCK (THREADS/32)
#define GRID    (NROWS / (ROWS_PER_WARP * WARPS_PER_BLOCK))   // 1024

__global__ __launch_bounds__(THREADS, 2)
void q6_kernel(const float* __restrict__ x,
               const float* __restrict__ W,
               const float* __restrict__ protos,
               const float* __restrict__ hs,
               float* __restrict__ out)
{
    __shared__ float w_s[KD * DDIM];   // 24 KB, layout [k][d]
    __shared__ float p_s[NP * 8];      // normalized prototypes, padded stride 8
    __shared__ float h_sh;

    const int tid = threadIdx.x;

    // ---- stage W into shared (coalesced float4 copy: 1536 float4 / 256 thr = 6 each)
    {
        const float4* Wv  = reinterpret_cast<const float4*>(W);
        float4*       wsv = reinterpret_cast<float4*>(w_s);
        #pragma unroll
        for (int i = 0; i < (KD * DDIM / 4) / THREADS; ++i)
            wsv[tid + i * THREADS] = Wv[tid + i * THREADS];
    }
    // ---- normalize prototypes into shared (8 threads, 6 floats each)
    if (tid < NP) {
        float pv[KD]; float ss = 0.f;
        #pragma unroll
        for (int k = 0; k < KD; ++k) { pv[k] = protos[tid * KD + k]; ss += pv[k] * pv[k]; }
        float inv = 1.f / fmaxf(sqrtf(ss), 1e-12f);
        #pragma unroll
        for (int k = 0; k < KD; ++k) p_s[tid * 8 + k] = pv[k] * inv;
    }
    if (tid == 0) h_sh = hs[0];
    __syncthreads();

    const int warp = tid >> 5;
    const int lane = tid & 31;
    const int gw   = blockIdx.x * WARPS_PER_BLOCK + warp;
    const int row0 = gw * ROWS_PER_WARP;
    if (row0 >= NROWS) return;

    // ---- main GEMV: 4 rows per warp, 24 accumulators per lane
    float s[ROWS_PER_WARP][KD];
    #pragma unroll
    for (int r = 0; r < ROWS_PER_WARP; ++r)
        #pragma unroll
        for (int k = 0; k < KD; ++k) s[r][k] = 0.f;

    const float4* xv  = reinterpret_cast<const float4*>(x + (size_t)row0 * DDIM);
    const float4* wv4 = reinterpret_cast<const float4*>(w_s);

    #pragma unroll
    for (int c = 0; c < DDIM / 128; ++c) {          // 8 chunks of 128 floats
        const int dq = c * 32 + lane;               // float4 index within row
        float4 a0 = xv[0 * (DDIM/4) + dq];
        float4 a1 = xv[1 * (DDIM/4) + dq];
        float4 a2 = xv[2 * (DDIM/4) + dq];
        float4 a3 = xv[3 * (DDIM/4) + dq];
        #pragma unroll
        for (int k = 0; k < KD; ++k) {
            const float4 w4 = wv4[k * (DDIM/4) + dq];
            s[0][k] = fmaf(a0.x, w4.x, s[0][k]); s[0][k] = fmaf(a0.y, w4.y, s[0][k]);
            s[0][k] = fmaf(a0.z, w4.z, s[0][k]); s[0][k] = fmaf(a0.w, w4.w, s[0][k]);
            s[1][k] = fmaf(a1.x, w4.x, s[1][k]); s[1][k] = fmaf(a1.y, w4.y, s[1][k]);
            s[1][k] = fmaf(a1.z, w4.z, s[1][k]); s[1][k] = fmaf(a1.w, w4.w, s[1][k]);
            s[2][k] = fmaf(a2.x, w4.x, s[2][k]); s[2][k] = fmaf(a2.y, w4.y, s[2][k]);
            s[2][k] = fmaf(a2.z, w4.z, s[2][k]); s[2][k] = fmaf(a2.w, w4.w, s[2][k]);
            s[3][k] = fmaf(a3.x, w4.x, s[3][k]); s[3][k] = fmaf(a3.y, w4.y, s[3][k]);
            s[3][k] = fmaf(a3.z, w4.z, s[3][k]); s[3][k] = fmaf(a3.w, w4.w, s[3][k]);
        }
    }

    // ---- warp butterfly reduce: all lanes end with the full 24 sums
    #pragma unroll
    for (int off = 16; off > 0; off >>= 1)
        #pragma unroll
        for (int r = 0; r < ROWS_PER_WARP; ++r)
            #pragma unroll
            for (int k = 0; k < KD; ++k)
                s[r][k] += __shfl_xor_sync(0xffffffffu, s[r][k], off);

    // ---- epilogue: lanes 0..3 each finalize one row. Compile-time-unrolled
    //      ternary chain per k -> SEL instructions, no runtime-indexed register
    //      array, no local-memory spill.
    if (lane < ROWS_PER_WARP) {
        float zs[KD];
        #pragma unroll
        for (int k = 0; k < KD; ++k) {
            zs[k] = (lane == 1) ? s[1][k]
                  : (lane == 2) ? s[2][k]
                  : (lane == 3) ? s[3][k]
                  :               s[0][k];
        }

        // tanh + L2 normalize (clamp 1e-6)
        float ss = 0.f;
        #pragma unroll
        for (int k = 0; k < KD; ++k) { zs[k] = tanhf(zs[k]); ss += zs[k] * zs[k]; }
        const float invn = 1.f / fmaxf(sqrtf(ss), 1e-6f);

        // logits = -h * (3 - 3*dot_normed)  -> softmax-equivalent to (3*h*invn) * dot
        const float scale = 3.f * h_sh * invn;
        float lg[NP]; float mx = -1e30f;
        #pragma unroll
        for (int p = 0; p < NP; ++p) {
            float d = 0.f;
            #pragma unroll
            for (int k = 0; k < KD; ++k) d = fmaf(zs[k], p_s[p * 8 + k], d);
            lg[p] = scale * d;
            mx = fmaxf(mx, lg[p]);
        }
        float se = 0.f;
        #pragma unroll
        for (int p = 0; p < NP; ++p) { lg[p] = __expf(lg[p] - mx); se += lg[p]; }
        const float is = 1.f / se;

        const int row = row0 + lane;
        float4* o = reinterpret_cast<float4*>(out + (size_t)row * NP);
        o[0] = make_float4(lg[0] * is, lg[1] * is, lg[2] * is, lg[3] * is);
        o[1] = make_float4(lg[4] * is, lg[5] * is, lg[6] * is, lg[7] * is);
    }
}

extern "C" void kernel_launch(void* const* d_in, const int* in_sizes, int n_in,
                              void* d_out, int out_size)
{
    const float* x      = (const float*)d_in[0];   // (4,8192,1024) f32
    const float* W      = (const float*)d_in[1];   // (6,1024) f32
    const float* protos = (const float*)d_in[2];   // (8,6) f32
    const float* hs     = (const float*)d_in[3];   // scalar f32
    float*       out    = (float*)d_out;           // (4,8192,8) f32

    q6_kernel<<<GRID, THREADS>>>(x, W, protos, hs, out);
}

// round 11
// speedup vs baseline: 1.2271x; 1.2271x over previous
#include <cuda_runtime.h>
#include <math.h>
#include <stdint.h>

// Problem shape (fixed by the dataset)
#define NROWS   32768      // B*T = 4*8192
#define DDIM    1024
#define KD      6
#define NP      8
#define ROWS_PER_WARP 4
#define THREADS 256
#define WARPS_PER_BLOCK (THREADS/32)
#define GRID    (NROWS / (ROWS_PER_WARP * WARPS_PER_BLOCK))   // 1024

typedef unsigned long long u64;

// Packed dual-FMA (sm_103a FFMA2). acc.{lo,hi} += a.{lo,hi} * b.{lo,hi}
__device__ __forceinline__ void ffma2(u64& acc, u64 a, u64 b) {
    asm("fma.rn.f32x2 %0, %1, %2, %0;" : "+l"(acc) : "l"(a), "l"(b));
}
// Horizontal sum of a packed f32x2
__device__ __forceinline__ float f32x2_sum(u64 v) {
    uint32_t lo, hi;
    asm("mov.b64 {%0, %1}, %2;" : "=r"(lo), "=r"(hi) : "l"(v));
    return __uint_as_float(lo) + __uint_as_float(hi);
}

__global__ __launch_bounds__(THREADS, 3)
void q6_kernel(const float* __restrict__ x,
               const float* __restrict__ W,
               const float* __restrict__ protos,
               const float* __restrict__ hs,
               float* __restrict__ out)
{
    __shared__ float w_s[KD * DDIM];   // 24 KB, layout [k][d]
    __shared__ float p_s[NP * 8];      // normalized prototypes, padded stride 8
    __shared__ float h_sh;

    const int tid = threadIdx.x;

    // ---- stage W into shared (coalesced float4 copy)
    {
        const float4* Wv  = reinterpret_cast<const float4*>(W);
        float4*       wsv = reinterpret_cast<float4*>(w_s);
        #pragma unroll
        for (int i = 0; i < (KD * DDIM / 4) / THREADS; ++i)
            wsv[tid + i * THREADS] = Wv[tid + i * THREADS];
    }
    // ---- normalize prototypes into shared
    if (tid < NP) {
        float pv[KD]; float ss = 0.f;
        #pragma unroll
        for (int k = 0; k < KD; ++k) { pv[k] = protos[tid * KD + k]; ss += pv[k] * pv[k]; }
        float inv = 1.f / fmaxf(sqrtf(ss), 1e-12f);
        #pragma unroll
        for (int k = 0; k < KD; ++k) p_s[tid * 8 + k] = pv[k] * inv;
    }
    if (tid == 0) h_sh = hs[0];
    __syncthreads();

    const int warp = tid >> 5;
    const int lane = tid & 31;
    const int gw   = blockIdx.x * WARPS_PER_BLOCK + warp;
    const int row0 = gw * ROWS_PER_WARP;
    if (row0 >= NROWS) return;

    // ---- main GEMV: 4 rows per warp, 24 packed f32x2 accumulators per lane
    u64 s2[ROWS_PER_WARP][KD];
    #pragma unroll
    for (int r = 0; r < ROWS_PER_WARP; ++r)
        #pragma unroll
        for (int k = 0; k < KD; ++k) s2[r][k] = 0ULL;   // (0.0f, 0.0f)

    const ulonglong2* xv  = reinterpret_cast<const ulonglong2*>(x + (size_t)row0 * DDIM);
    const ulonglong2* wv2 = reinterpret_cast<const ulonglong2*>(w_s);

    #pragma unroll
    for (int c = 0; c < DDIM / 128; ++c) {          // 8 chunks of 128 floats
        const int dq = c * 32 + lane;               // 16B-vector index within row
        ulonglong2 a0 = xv[0 * (DDIM/4) + dq];
        ulonglong2 a1 = xv[1 * (DDIM/4) + dq];
        ulonglong2 a2 = xv[2 * (DDIM/4) + dq];
        ulonglong2 a3 = xv[3 * (DDIM/4) + dq];
        #pragma unroll
        for (int k = 0; k < KD; ++k) {
            const ulonglong2 w2 = wv2[k * (DDIM/4) + dq];
            ffma2(s2[0][k], a0.x, w2.x); ffma2(s2[0][k], a0.y, w2.y);
            ffma2(s2[1][k], a1.x, w2.x); ffma2(s2[1][k], a1.y, w2.y);
            ffma2(s2[2][k], a2.x, w2.x); ffma2(s2[2][k], a2.y, w2.y);
            ffma2(s2[3][k], a3.x, w2.x); ffma2(s2[3][k], a3.y, w2.y);
        }
    }

    // ---- collapse packed pairs, then warp butterfly reduce
    float s[ROWS_PER_WARP][KD];
    #pragma unroll
    for (int r = 0; r < ROWS_PER_WARP; ++r)
        #pragma unroll
        for (int k = 0; k < KD; ++k) s[r][k] = f32x2_sum(s2[r][k]);

    #pragma unroll
    for (int off = 16; off > 0; off >>= 1)
        #pragma unroll
        for (int r = 0; r < ROWS_PER_WARP; ++r)
            #pragma unroll
            for (int k = 0; k < KD; ++k)
                s[r][k] += __shfl_xor_sync(0xffffffffu, s[r][k], off);

    // ---- epilogue: lanes 0..3 each finalize one row (SEL chain, no spills)
    if (lane < ROWS_PER_WARP) {
        float zs[KD];
        #pragma unroll
        for (int k = 0; k < KD; ++k) {
            zs[k] = (lane == 1) ? s[1][k]
                  : (lane == 2) ? s[2][k]
                  : (lane == 3) ? s[3][k]
                  :               s[0][k];
        }

        // tanh + L2 normalize (clamp 1e-6)
        float ss = 0.f;
        #pragma unroll
        for (int k = 0; k < KD; ++k) { zs[k] = tanhf(zs[k]); ss += zs[k] * zs[k]; }
        const float invn = 1.f / fmaxf(sqrtf(ss), 1e-6f);

        // softmax of -h*(3 - 3*dot) == softmax of (3*h*invn)*dot  (shift-invariant)
        const float scale = 3.f * h_sh * invn;
        float lg[NP]; float mx = -1e30f;
        #pragma unroll
        for (int p = 0; p < NP; ++p) {
            float d = 0.f;
            #pragma unroll
            for (int k = 0; k < KD; ++k) d = fmaf(zs[k], p_s[p * 8 + k], d);
            lg[p] = scale * d;
            mx = fmaxf(mx, lg[p]);
        }
        float se = 0.f;
        #pragma unroll
        for (int p = 0; p < NP; ++p) { lg[p] = __expf(lg[p] - mx); se += lg[p]; }
        const float is = 1.f / se;

        const int row = row0 + lane;
        float4* o = reinterpret_cast<float4*>(out + (size_t)row * NP);
        o[0] = make_float4(lg[0] * is, lg[1] * is, lg[2] * is, lg[3] * is);
        o[1] = make_float4(lg[4] * is, lg[5] * is, lg[6] * is, lg[7] * is);
    }
}

extern "C" void kernel_launch(void* const* d_in, const int* in_sizes, int n_in,
                              void* d_out, int out_size)
{
    const float* x      = (const float*)d_in[0];   // (4,8192,1024) f32
    const float* W      = (const float*)d_in[1];   // (6,1024) f32
    const float* protos = (const float*)d_in[2];   // (8,6) f32
    const float* hs     = (const float*)d_in[3];   // scalar f32
    float*       out    = (float*)d_out;           // (4,8192,8) f32

    q6_kernel<<<GRID, THREADS>>>(x, W, protos, hs, out);
}

// round 12
// speedup vs baseline: 1.2398x; 1.0104x over previous
#include <cuda_runtime.h>
#include <math.h>
#include <stdint.h>

// Problem shape (fixed by the dataset)
#define NROWS   32768      // B*T = 4*8192
#define DDIM    1024
#define KD      6
#define NP      8
#define ROWS_PER_WARP 4
#define THREADS 256
#define WARPS_PER_BLOCK (THREADS/32)
#define ROWS_PER_CTA (ROWS_PER_WARP*WARPS_PER_BLOCK)          // 32
#define GRID    (NROWS / ROWS_PER_CTA)                        // 1024
#define CHUNK   128                                           // floats per row per stage
#define NCHUNKS (DDIM / CHUNK)                                // 8
#define STAGE_FLOATS (ROWS_PER_CTA * CHUNK)                   // 4096
// dynamic smem layout (floats): W[6144] | xbuf[2*4096] | p_s[64] | h[1]
#define SM_W    0
#define SM_XB   (KD * DDIM)
#define SM_PS   (SM_XB + 2 * STAGE_FLOATS)
#define SM_H    (SM_PS + NP * 8)
#define SMEM_FLOATS (SM_H + 1)
#define SMEM_BYTES  (SMEM_FLOATS * 4)

typedef unsigned long long u64;

// Packed dual-FMA (sm_103a FFMA2). acc.{lo,hi} += a.{lo,hi} * b.{lo,hi}
__device__ __forceinline__ void ffma2(u64& acc, u64 a, u64 b) {
    asm("fma.rn.f32x2 %0, %1, %2, %0;" : "+l"(acc) : "l"(a), "l"(b));
}
__device__ __forceinline__ float f32x2_sum(u64 v) {
    uint32_t lo, hi;
    asm("mov.b64 {%0, %1}, %2;" : "=r"(lo), "=r"(hi) : "l"(v));
    return __uint_as_float(lo) + __uint_as_float(hi);
}
// 16-byte async copy gmem -> smem (LDGSTS)
__device__ __forceinline__ void cp16(uint32_t saddr, const float* gaddr) {
    asm volatile("cp.async.cg.shared.global [%0], [%1], 16;" :: "r"(saddr), "l"(gaddr));
}
__device__ __forceinline__ void cp_commit() {
    asm volatile("cp.async.commit_group;");
}
template <int N>
__device__ __forceinline__ void cp_wait() {
    asm volatile("cp.async.wait_group %0;" :: "n"(N));
}

__global__ __launch_bounds__(THREADS, 3)
void q6_kernel(const float* __restrict__ x,
               const float* __restrict__ W,
               const float* __restrict__ protos,
               const float* __restrict__ hs,
               float* __restrict__ out)
{
    extern __shared__ float smem[];
    float* w_s = smem + SM_W;
    float* xb  = smem + SM_XB;
    float* p_s = smem + SM_PS;

    const int tid  = threadIdx.x;
    const int warp = tid >> 5;
    const int lane = tid & 31;
    const int cta_row0 = blockIdx.x * ROWS_PER_CTA;

    const uint32_t xb_sa = (uint32_t)__cvta_generic_to_shared(xb);

    // ---- kick off stage 0 of x immediately (16KB, 4 x 16B per thread)
    {
        #pragma unroll
        for (int i = 0; i < STAGE_FLOATS / 4 / THREADS; ++i) {
            const int s   = tid + i * THREADS;        // 16B slot 0..1023
            const int row = s >> 5, vec = s & 31;
            cp16(xb_sa + (uint32_t)s * 16u,
                 x + (size_t)(cta_row0 + row) * DDIM + vec * 4);
        }
        cp_commit();
    }

    // ---- stage W into shared (coalesced float4 copy)
    {
        const float4* Wv  = reinterpret_cast<const float4*>(W);
        float4*       wsv = reinterpret_cast<float4*>(w_s);
        #pragma unroll
        for (int i = 0; i < (KD * DDIM / 4) / THREADS; ++i)
            wsv[tid + i * THREADS] = Wv[tid + i * THREADS];
    }
    // ---- normalize prototypes into shared
    if (tid < NP) {
        float pv[KD]; float ss = 0.f;
        #pragma unroll
        for (int k = 0; k < KD; ++k) { pv[k] = protos[tid * KD + k]; ss += pv[k] * pv[k]; }
        float inv = 1.f / fmaxf(sqrtf(ss), 1e-12f);
        #pragma unroll
        for (int k = 0; k < KD; ++k) p_s[tid * 8 + k] = pv[k] * inv;
    }
    if (tid == 0) smem[SM_H] = hs[0];

    // ---- accumulators: 4 rows x 6 k, packed f32x2
    u64 s2[ROWS_PER_WARP][KD];
    #pragma unroll
    for (int r = 0; r < ROWS_PER_WARP; ++r)
        #pragma unroll
        for (int k = 0; k < KD; ++k) s2[r][k] = 0ULL;

    const ulonglong2* wv2 = reinterpret_cast<const ulonglong2*>(w_s);
    const int rbase = warp * ROWS_PER_WARP;           // this warp's rows in the stage

    #pragma unroll
    for (int c = 0; c < NCHUNKS; ++c) {
        // issue next stage into the other buffer (prev compute on that buffer
        // finished before the previous iteration's trailing barrier)
        if (c + 1 < NCHUNKS) {
            const uint32_t dst = xb_sa + (uint32_t)(((c + 1) & 1) * STAGE_FLOATS) * 4u;
            #pragma unroll
            for (int i = 0; i < STAGE_FLOATS / 4 / THREADS; ++i) {
                const int s   = tid + i * THREADS;
                const int row = s >> 5, vec = s & 31;
                cp16(dst + (uint32_t)s * 16u,
                     x + (size_t)(cta_row0 + row) * DDIM + (c + 1) * CHUNK + vec * 4);
            }
            cp_commit();
            cp_wait<1>();     // stage c complete (newest group still in flight)
        } else {
            cp_wait<0>();     // last stage: drain everything
        }
        __syncthreads();      // stage c visible CTA-wide (also covers W/p_s on c==0)

        // compute stage c
        const ulonglong2* xs = reinterpret_cast<const ulonglong2*>(xb + (c & 1) * STAGE_FLOATS);
        const ulonglong2 a0 = xs[(rbase + 0) * 32 + lane];
        const ulonglong2 a1 = xs[(rbase + 1) * 32 + lane];
        const ulonglong2 a2 = xs[(rbase + 2) * 32 + lane];
        const ulonglong2 a3 = xs[(rbase + 3) * 32 + lane];
        #pragma unroll
        for (int k = 0; k < KD; ++k) {
            const ulonglong2 w2 = wv2[k * (DDIM / 4) + c * 32 + lane];
            ffma2(s2[0][k], a0.x, w2.x); ffma2(s2[0][k], a0.y, w2.y);
            ffma2(s2[1][k], a1.x, w2.x); ffma2(s2[1][k], a1.y, w2.y);
            ffma2(s2[2][k], a2.x, w2.x); ffma2(s2[2][k], a2.y, w2.y);
            ffma2(s2[3][k], a3.x, w2.x); ffma2(s2[3][k], a3.y, w2.y);
        }
        __syncthreads();      // all warps done with stage c before its buffer is reused
    }

    // ---- collapse packed pairs, then warp butterfly reduce
    float s[ROWS_PER_WARP][KD];
    #pragma unroll
    for (int r = 0; r < ROWS_PER_WARP; ++r)
        #pragma unroll
        for (int k = 0; k < KD; ++k) s[r][k] = f32x2_sum(s2[r][k]);

    #pragma unroll
    for (int off = 16; off > 0; off >>= 1)
        #pragma unroll
        for (int r = 0; r < ROWS_PER_WARP; ++r)
            #pragma unroll
            for (int k = 0; k < KD; ++k)
                s[r][k] += __shfl_xor_sync(0xffffffffu, s[r][k], off);

    // ---- epilogue: lanes 0..3 each finalize one row
    if (lane < ROWS_PER_WARP) {
        float zs[KD];
        #pragma unroll
        for (int k = 0; k < KD; ++k) {
            zs[k] = (lane == 1) ? s[1][k]
                  : (lane == 2) ? s[2][k]
                  : (lane == 3) ? s[3][k]
                  :               s[0][k];
        }

        float ss = 0.f;
        #pragma unroll
        for (int k = 0; k < KD; ++k) { zs[k] = tanhf(zs[k]); ss += zs[k] * zs[k]; }
        const float invn = 1.f / fmaxf(sqrtf(ss), 1e-6f);

        // softmax of -h*(3 - 3*dot) == softmax of (3*h*invn)*dot
        const float scale = 3.f * smem[SM_H] * invn;
        float lg[NP]; float mx = -1e30f;
        #pragma unroll
        for (int p = 0; p < NP; ++p) {
            float d = 0.f;
            #pragma unroll
            for (int k = 0; k < KD; ++k) d = fmaf(zs[k], p_s[p * 8 + k], d);
            lg[p] = scale * d;
            mx = fmaxf(mx, lg[p]);
        }
        float se = 0.f;
        #pragma unroll
        for (int p = 0; p < NP; ++p) { lg[p] = __expf(lg[p] - mx); se += lg[p]; }
        const float is = 1.f / se;

        const int row = cta_row0 + rbase + lane;
        float4* o = reinterpret_cast<float4*>(out + (size_t)row * NP);
        o[0] = make_float4(lg[0] * is, lg[1] * is, lg[2] * is, lg[3] * is);
        o[1] = make_float4(lg[4] * is, lg[5] * is, lg[6] * is, lg[7] * is);
    }
}

extern "C" void kernel_launch(void* const* d_in, const int* in_sizes, int n_in,
                              void* d_out, int out_size)
{
    const float* x      = (const float*)d_in[0];   // (4,8192,1024) f32
    const float* W      = (const float*)d_in[1];   // (6,1024) f32
    const float* protos = (const float*)d_in[2];   // (8,6) f32
    const float* hs     = (const float*)d_in[3];   // scalar f32
    float*       out    = (float*)d_out;           // (4,8192,8) f32

    // opt in to >48KB dynamic smem (attribute set, not an allocation; idempotent)
    cudaFuncSetAttribute(q6_kernel, cudaFuncAttributeMaxDynamicSharedMemorySize, SMEM_BYTES);

    q6_kernel<<<GRID, THREADS, SMEM_BYTES>>>(x, W, protos, hs, out);
}